// round 7
// baseline (speedup 1.0000x reference)
#include <cuda_runtime.h>
#include <cstdint>

// SpikingLayer: [2048,16384] fp32 = [T=64, B=32, F=16384]; per (b,f):
//   s = (x + s) - a;  s = max(s+1,0) - 1;  a = (s>0) ? floor(s) : 0   (bit-exact)
//
// DRAM-bound at the ~5.75 TB/s mixed r/w ceiling. This round: Blackwell
// 256-bit LDG/STG (.v8.b32) — the only width where inline L2::evict_last /
// evict_first qualifiers are legal on sm_103a (per ptxas). Halves memory
// instruction count, 1024B/warp bursts, and retests L2 retention through the
// instruction-encoded hint path instead of createpolicy.

#define BF8 (32 * 16384 / 8)   // B*F 8-float lanes = 65536
#define TSTEPS 64

struct f8 { float4 a, b; };

__device__ __forceinline__ f8 ld256_last(const float* p) {
    f8 v;
    asm volatile("ld.global.L2::evict_last.v8.b32 {%0,%1,%2,%3,%4,%5,%6,%7}, [%8];"
                 : "=f"(v.a.x), "=f"(v.a.y), "=f"(v.a.z), "=f"(v.a.w),
                   "=f"(v.b.x), "=f"(v.b.y), "=f"(v.b.z), "=f"(v.b.w)
                 : "l"(p));
    return v;
}

__device__ __forceinline__ void st256_first(float* p, const f8& v) {
    asm volatile("st.global.L2::evict_first.v8.b32 [%0], {%1,%2,%3,%4,%5,%6,%7,%8};"
                 :: "l"(p),
                    "f"(v.a.x), "f"(v.a.y), "f"(v.a.z), "f"(v.a.w),
                    "f"(v.b.x), "f"(v.b.y), "f"(v.b.z), "f"(v.b.w)
                 : "memory");
}

__global__ __launch_bounds__(256)
void spiking_layer_kernel(const float* __restrict__ in,
                          float* __restrict__ out) {
    const int i = blockIdx.x * blockDim.x + threadIdx.x;   // 0 .. BF8-1

    f8 s, a;
    s.a = make_float4(0.f, 0.f, 0.f, 0.f); s.b = s.a;
    a.a = s.a; a.b = s.a;

    long long off = (long long)i * 8;            // float offset of this lane-group
    const long long STRIDE = (long long)BF8 * 8; // floats per time step

    f8 x0 = ld256_last(in + off);                // t = 0
    f8 x1 = ld256_last(in + off + STRIDE);       // t = 1 (in flight)

    #pragma unroll
    for (int t = 0; t < TSTEPS; ++t) {
        f8 x2;
        if (t < TSTEPS - 2) {
            x2 = ld256_last(in + off + 2 * STRIDE);  // prefetch t+2
        }

        // membrane update: (x + s) - a, exact reference order
        s.a.x = (x0.a.x + s.a.x) - a.a.x;
        s.a.y = (x0.a.y + s.a.y) - a.a.y;
        s.a.z = (x0.a.z + s.a.z) - a.a.z;
        s.a.w = (x0.a.w + s.a.w) - a.a.w;
        s.b.x = (x0.b.x + s.b.x) - a.b.x;
        s.b.y = (x0.b.y + s.b.y) - a.b.y;
        s.b.z = (x0.b.z + s.b.z) - a.b.z;
        s.b.w = (x0.b.w + s.b.w) - a.b.w;

        // lower clamp in reference order: relu(s + 1) - 1 (NOT max(s,-1))
        s.a.x = fmaxf(s.a.x + 1.0f, 0.0f) - 1.0f;
        s.a.y = fmaxf(s.a.y + 1.0f, 0.0f) - 1.0f;
        s.a.z = fmaxf(s.a.z + 1.0f, 0.0f) - 1.0f;
        s.a.w = fmaxf(s.a.w + 1.0f, 0.0f) - 1.0f;
        s.b.x = fmaxf(s.b.x + 1.0f, 0.0f) - 1.0f;
        s.b.y = fmaxf(s.b.y + 1.0f, 0.0f) - 1.0f;
        s.b.z = fmaxf(s.b.z + 1.0f, 0.0f) - 1.0f;
        s.b.w = fmaxf(s.b.w + 1.0f, 0.0f) - 1.0f;

        // threshold-subtract spikes: floor(s) when s > 0, else 0
        a.a.x = (s.a.x > 0.f) ? floorf(s.a.x) : 0.f;
        a.a.y = (s.a.y > 0.f) ? floorf(s.a.y) : 0.f;
        a.a.z = (s.a.z > 0.f) ? floorf(s.a.z) : 0.f;
        a.a.w = (s.a.w > 0.f) ? floorf(s.a.w) : 0.f;
        a.b.x = (s.b.x > 0.f) ? floorf(s.b.x) : 0.f;
        a.b.y = (s.b.y > 0.f) ? floorf(s.b.y) : 0.f;
        a.b.z = (s.b.z > 0.f) ? floorf(s.b.z) : 0.f;
        a.b.w = (s.b.w > 0.f) ? floorf(s.b.w) : 0.f;

        st256_first(out + off, a);

        off += STRIDE;
        x0 = x1;
        x1 = x2;
    }
}

extern "C" void kernel_launch(void* const* d_in, const int* in_sizes, int n_in,
                              void* d_out, int out_size) {
    const float* in = (const float*)d_in[0];
    float* out = (float*)d_out;

    const int threads = 256;
    const int blocks = BF8 / threads;      // 256
    spiking_layer_kernel<<<blocks, threads>>>(in, out);
}